// round 5
// baseline (speedup 1.0000x reference)
#include <cuda_runtime.h>
#include <cuda_fp16.h>
#include <mma.h>
#include <cstdint>

using namespace nvcuda;

#define NPTS 65536
#define DIN 256
#define DOUT 256
#define NHEAD 8
#define DH 32
#define NTRK 256
#define LSEQ 256

// Scratch (device globals -- no allocations allowed)
__device__ __half g_valh[(size_t)NPTS * DIN];
__device__ __half g_wqkvh[3 * DOUT * DIN];
__device__ __half g_wlinh[DOUT * DIN];
__device__ __half g_qkvh[(size_t)NPTS * 3 * DOUT];
__device__ __half g_ctxh[(size_t)NPTS * DOUT];

// ---------------------------------------------------------------------------
__device__ __forceinline__ uint32_t smem_u32(const void* p) {
    uint32_t a;
    asm("{ .reg .u64 t; cvta.to.shared.u64 t, %1; cvt.u32.u64 %0, t; }" : "=r"(a) : "l"(p));
    return a;
}
__device__ __forceinline__ void cp_async16_s(uint32_t smem, const void* gmem) {
    asm volatile("cp.async.cg.shared.global [%0], [%1], 16;\n" :: "r"(smem), "l"(gmem));
}
__device__ __forceinline__ void cp_commit() { asm volatile("cp.async.commit_group;\n"); }
template <int N> __device__ __forceinline__ void cp_wait() {
    asm volatile("cp.async.wait_group %0;\n" :: "n"(N));
}

// ---------------------------------------------------------------------------
// fp32 -> fp16 convert
// ---------------------------------------------------------------------------
__global__ void f2h_kernel(const float* __restrict__ in, __half* __restrict__ out, int n4) {
    int i = blockIdx.x * blockDim.x + threadIdx.x;
    if (i < n4) {
        float4 v = reinterpret_cast<const float4*>(in)[i];
        reinterpret_cast<__half2*>(out)[2 * i]     = __floats2half2_rn(v.x, v.y);
        reinterpret_cast<__half2*>(out)[2 * i + 1] = __floats2half2_rn(v.z, v.w);
    }
}

// ---------------------------------------------------------------------------
// GEMM: C[M,Nc] = A[M,K] @ W^T + bias. W row-major [Nc,K]. K == 256.
// BM=128 BN=128 BK=64, 3-stage cp.async, 8 warps (2x4), warp tile 64x32.
// One __syncthreads per mainloop iteration.
// ---------------------------------------------------------------------------
template <bool OUT_HALF>
__global__ __launch_bounds__(256) void gemm_bias_kernel(
    const __half* __restrict__ A, const __half* __restrict__ W,
    const float* __restrict__ bias, void* __restrict__ Cout,
    int M, int Nc, int K)
{
    constexpr int BM = 128, BN = 128, BK = 64, LDT = 72, LDC = 36;
    constexpr int STAGE_H = (BM + BN) * LDT;                 // halves per stage (36864 B)
    extern __shared__ __align__(16) unsigned char smbuf[];   // 3 stages = 110592 B
    __half* smh = reinterpret_cast<__half*>(smbuf);

    const int tid = threadIdx.x;
    const int lane = tid & 31, warp = tid >> 5;
    const int wr = warp >> 2, wc = warp & 3;                 // 2x4 warp grid
    const int rowBase = blockIdx.y * BM;
    const int colBase = blockIdx.x * BN;

    auto load_stage = [&](int s, int kb) {
        __half* St = smh + s * STAGE_H;
        const __half* Ag = A + (size_t)rowBase * K + kb * BK;
        const __half* Wg = W + (size_t)colBase * K + kb * BK;
#pragma unroll
        for (int i = 0; i < 8; i++) {
            int idx = tid + i * 256;               // 0..2047
            int r = idx >> 3, c = idx & 7;
            const __half* src = (r < BM) ? (Ag + (size_t)r * K + c * 8)
                                         : (Wg + (size_t)(r - BM) * K + c * 8);
            cp_async16_s(smem_u32(St + r * LDT + c * 8), src);
        }
        cp_commit();
    };

    wmma::fragment<wmma::accumulator, 16, 16, 16, float> acc[4][2];
#pragma unroll
    for (int i = 0; i < 4; i++)
#pragma unroll
        for (int j = 0; j < 2; j++) wmma::fill_fragment(acc[i][j], 0.0f);

    load_stage(0, 0);
    load_stage(1, 1);

#pragma unroll
    for (int kb = 0; kb < 4; kb++) {               // K = 256 = 4 * BK
        if (kb < 3) cp_wait<1>(); else cp_wait<0>();
        __syncthreads();
        if (kb + 2 < 4) load_stage((kb + 2) % 3, kb + 2);

        const __half* As = smh + (kb % 3) * STAGE_H;
        const __half* Bs = As + BM * LDT;
#pragma unroll
        for (int kk = 0; kk < BK; kk += 16) {
            wmma::fragment<wmma::matrix_a, 16, 16, 16, __half, wmma::row_major> af[4];
#pragma unroll
            for (int i = 0; i < 4; i++)
                wmma::load_matrix_sync(af[i], As + (wr * 64 + i * 16) * LDT + kk, LDT);
#pragma unroll
            for (int j = 0; j < 2; j++) {
                wmma::fragment<wmma::matrix_b, 16, 16, 16, __half, wmma::col_major> bf;
                wmma::load_matrix_sync(bf, Bs + (wc * 32 + j * 16) * LDT + kk, LDT);
#pragma unroll
                for (int i = 0; i < 4; i++)
                    wmma::mma_sync(acc[i][j], af[i], bf, acc[i][j]);
            }
        }
    }
    __syncthreads();   // protect smem reuse by epilogue staging

    // epilogue via smem staging (64x36 fp32 per warp)
    float* Cw = reinterpret_cast<float*>(smbuf) + warp * (64 * LDC);
#pragma unroll
    for (int i = 0; i < 4; i++)
#pragma unroll
        for (int j = 0; j < 2; j++)
            wmma::store_matrix_sync(Cw + i * 16 * LDC + j * 16, acc[i][j], LDC, wmma::mem_row_major);
    __syncwarp();

    const int gc = colBase + wc * 32;
#pragma unroll
    for (int rr = 0; rr < 2; rr++) {
        const int row = lane + rr * 32;
        const int gr = rowBase + wr * 64 + row;
        const float* cr = Cw + row * LDC;
        if (OUT_HALF) {
            __half* dst = reinterpret_cast<__half*>(Cout) + (size_t)gr * Nc + gc;
#pragma unroll
            for (int c = 0; c < 32; c += 2)
                *reinterpret_cast<__half2*>(dst + c) =
                    __floats2half2_rn(cr[c] + bias[gc + c], cr[c + 1] + bias[gc + c + 1]);
        } else {
            float* dst = reinterpret_cast<float*>(Cout) + (size_t)gr * Nc + gc;
#pragma unroll
            for (int c = 0; c < 32; c++) dst[c] = cr[c] + bias[gc + c];
        }
    }
}

// ---------------------------------------------------------------------------
// Attention: one block per (track, head); wmma QK^T with register softmax;
// unnormalized fp16 probs; PV wmma; normalize in epilogue.
// ---------------------------------------------------------------------------
__global__ __launch_bounds__(256) void attn_kernel(const __half* __restrict__ qkv,
                                                   __half* __restrict__ ctxout)
{
    constexpr int LDK = 40, LDP = 264;
    extern __shared__ __align__(16) unsigned char smbuf[];
    __half* Ksm = reinterpret_cast<__half*>(smbuf);
    __half* Vsm = Ksm + 256 * LDK;
    __half* Qsm = Vsm + 256 * LDK;
    __half* Psm = Qsm + 64 * LDK;
    float*  redM = reinterpret_cast<float*>(smbuf + 79872);
    float*  redS = redM + 128;

    const int tid = threadIdx.x, lane = tid & 31, warp = tid >> 5;
    const int g = lane >> 2, t4 = lane & 3;
    const int t = blockIdx.x >> 3, h = blockIdx.x & 7;
    const float scale = 0.17677669529663687f;

    {
        const uint4* ks = reinterpret_cast<const uint4*>(qkv + (size_t)(t * LSEQ + tid) * 768 + 256 + h * DH);
        const uint4* vs = reinterpret_cast<const uint4*>(qkv + (size_t)(t * LSEQ + tid) * 768 + 512 + h * DH);
        uint4* kd = reinterpret_cast<uint4*>(Ksm + tid * LDK);
        uint4* vd = reinterpret_cast<uint4*>(Vsm + tid * LDK);
#pragma unroll
        for (int q = 0; q < 4; q++) { kd[q] = ks[q]; vd[q] = vs[q]; }
    }

    for (int c0 = 0; c0 < LSEQ; c0 += 64) {
        {
            int r = tid >> 2, q = tid & 3;
            const uint4* qs = reinterpret_cast<const uint4*>(qkv + (size_t)(t * LSEQ + c0 + r) * 768 + h * DH);
            reinterpret_cast<uint4*>(Qsm + r * LDK)[q] = qs[q];
        }
        __syncthreads();

        const int wr = warp & 3, ch = warp >> 2;
        const int r0 = wr * 16, cb = ch * 128;
        wmma::fragment<wmma::accumulator, 16, 16, 16, float> S[8];
#pragma unroll
        for (int j = 0; j < 8; j++) wmma::fill_fragment(S[j], 0.0f);
#pragma unroll
        for (int kk = 0; kk < 32; kk += 16) {
            wmma::fragment<wmma::matrix_a, 16, 16, 16, __half, wmma::row_major> af;
            wmma::load_matrix_sync(af, Qsm + r0 * LDK + kk, LDK);
#pragma unroll
            for (int j = 0; j < 8; j++) {
                wmma::fragment<wmma::matrix_b, 16, 16, 16, __half, wmma::col_major> bf;
                wmma::load_matrix_sync(bf, Ksm + (cb + j * 16) * LDK + kk, LDK);
                wmma::mma_sync(S[j], af, bf, S[j]);
            }
        }

        float mx0 = -1e30f, mx1 = -1e30f;
#pragma unroll
        for (int j = 0; j < 8; j++) {
            mx0 = fmaxf(mx0, fmaxf(fmaxf(S[j].x[0], S[j].x[1]), fmaxf(S[j].x[4], S[j].x[5])));
            mx1 = fmaxf(mx1, fmaxf(fmaxf(S[j].x[2], S[j].x[3]), fmaxf(S[j].x[6], S[j].x[7])));
        }
#pragma unroll
        for (int o = 1; o <= 2; o <<= 1) {
            mx0 = fmaxf(mx0, __shfl_xor_sync(0xffffffffu, mx0, o));
            mx1 = fmaxf(mx1, __shfl_xor_sync(0xffffffffu, mx1, o));
        }
        if (t4 == 0) { redM[ch * 64 + r0 + g] = mx0; redM[ch * 64 + r0 + 8 + g] = mx1; }
        __syncthreads();

        const float gm0 = fmaxf(redM[r0 + g], redM[64 + r0 + g]);
        const float gm1 = fmaxf(redM[r0 + 8 + g], redM[64 + r0 + 8 + g]);

        float sm0 = 0.0f, sm1 = 0.0f;
#pragma unroll
        for (int j = 0; j < 8; j++) {
            float e0 = __expf((S[j].x[0] - gm0) * scale);
            float e1 = __expf((S[j].x[1] - gm0) * scale);
            float e2 = __expf((S[j].x[2] - gm1) * scale);
            float e3 = __expf((S[j].x[3] - gm1) * scale);
            float e4 = __expf((S[j].x[4] - gm0) * scale);
            float e5 = __expf((S[j].x[5] - gm0) * scale);
            float e6 = __expf((S[j].x[6] - gm1) * scale);
            float e7 = __expf((S[j].x[7] - gm1) * scale);
            sm0 += e0 + e1 + e4 + e5;
            sm1 += e2 + e3 + e6 + e7;
            __half2* p0 = reinterpret_cast<__half2*>(Psm + (r0 + g) * LDP + cb + j * 16 + 2 * t4);
            __half2* p1 = reinterpret_cast<__half2*>(Psm + (r0 + 8 + g) * LDP + cb + j * 16 + 2 * t4);
            p0[0] = __floats2half2_rn(e0, e1);
            p0[4] = __floats2half2_rn(e4, e5);
            p1[0] = __floats2half2_rn(e2, e3);
            p1[4] = __floats2half2_rn(e6, e7);
        }
#pragma unroll
        for (int o = 1; o <= 2; o <<= 1) {
            sm0 += __shfl_xor_sync(0xffffffffu, sm0, o);
            sm1 += __shfl_xor_sync(0xffffffffu, sm1, o);
        }
        if (t4 == 0) { redS[ch * 64 + r0 + g] = sm0; redS[ch * 64 + r0 + 8 + g] = sm1; }
        __syncthreads();

        {
            const int rp = (warp >> 1) * 16, cc = (warp & 1) * 16;
            wmma::fragment<wmma::accumulator, 16, 16, 16, float> O;
            wmma::fill_fragment(O, 0.0f);
#pragma unroll
            for (int kk = 0; kk < 256; kk += 16) {
                wmma::fragment<wmma::matrix_a, 16, 16, 16, __half, wmma::row_major> af;
                wmma::load_matrix_sync(af, Psm + rp * LDP + kk, LDP);
                wmma::fragment<wmma::matrix_b, 16, 16, 16, __half, wmma::row_major> bf;
                wmma::load_matrix_sync(bf, Vsm + kk * LDK + cc, LDK);
                wmma::mma_sync(O, af, bf, O);
            }
            const float inv0 = 1.0f / (redS[rp + g] + redS[64 + rp + g]);
            const float inv1 = 1.0f / (redS[rp + 8 + g] + redS[64 + rp + 8 + g]);
            __half* d0 = ctxout + (size_t)(t * LSEQ + c0 + rp + g) * DOUT + h * DH + cc + 2 * t4;
            __half* d1 = ctxout + (size_t)(t * LSEQ + c0 + rp + 8 + g) * DOUT + h * DH + cc + 2 * t4;
            *reinterpret_cast<__half2*>(d0)     = __floats2half2_rn(O.x[0] * inv0, O.x[1] * inv0);
            *reinterpret_cast<__half2*>(d0 + 8) = __floats2half2_rn(O.x[4] * inv0, O.x[5] * inv0);
            *reinterpret_cast<__half2*>(d1)     = __floats2half2_rn(O.x[2] * inv1, O.x[3] * inv1);
            *reinterpret_cast<__half2*>(d1 + 8) = __floats2half2_rn(O.x[6] * inv1, O.x[7] * inv1);
        }
        __syncthreads();
    }
}

// ---------------------------------------------------------------------------
extern "C" void kernel_launch(void* const* d_in, const int* in_sizes, int n_in,
                              void* d_out, int out_size)
{
    const float* values = (const float*)d_in[0];
    const float* wqkv   = (const float*)d_in[1];
    const float* bqkv   = (const float*)d_in[2];
    const float* wlin   = (const float*)d_in[3];
    const float* blin   = (const float*)d_in[4];

    void *p_valh, *p_wqkvh, *p_wlinh, *p_qkvh, *p_ctxh;
    cudaGetSymbolAddress(&p_valh, g_valh);
    cudaGetSymbolAddress(&p_wqkvh, g_wqkvh);
    cudaGetSymbolAddress(&p_wlinh, g_wlinh);
    cudaGetSymbolAddress(&p_qkvh, g_qkvh);
    cudaGetSymbolAddress(&p_ctxh, g_ctxh);

    const int GEMM_SMEM = 110592;
    cudaFuncSetAttribute(gemm_bias_kernel<true>,  cudaFuncAttributeMaxDynamicSharedMemorySize, GEMM_SMEM);
    cudaFuncSetAttribute(gemm_bias_kernel<false>, cudaFuncAttributeMaxDynamicSharedMemorySize, GEMM_SMEM);
    cudaFuncSetAttribute(attn_kernel, cudaFuncAttributeMaxDynamicSharedMemorySize, 80896);

    f2h_kernel<<<(NPTS * DIN / 4 + 255) / 256, 256>>>(values, (__half*)p_valh, NPTS * DIN / 4);
    f2h_kernel<<<(3 * DOUT * DIN / 4 + 255) / 256, 256>>>(wqkv, (__half*)p_wqkvh, 3 * DOUT * DIN / 4);
    f2h_kernel<<<(DOUT * DIN / 4 + 255) / 256, 256>>>(wlin, (__half*)p_wlinh, DOUT * DIN / 4);

    gemm_bias_kernel<true><<<dim3(768 / 128, NPTS / 128), 256, GEMM_SMEM>>>(
        (const __half*)p_valh, (const __half*)p_wqkvh, bqkv, p_qkvh, NPTS, 768, 256);

    attn_kernel<<<NTRK * NHEAD, 256, 80896>>>((const __half*)p_qkvh, (__half*)p_ctxh);

    gemm_bias_kernel<false><<<dim3(256 / 128, NPTS / 128), 256, GEMM_SMEM>>>(
        (const __half*)p_ctxh, (const __half*)p_wlinh, blin, d_out, NPTS, 256, 256);
}

// round 6
// speedup vs baseline: 1.7095x; 1.7095x over previous
#include <cuda_runtime.h>
#include <cuda_fp16.h>
#include <mma.h>
#include <cstdint>

using namespace nvcuda;

#define NPTS 65536
#define DIN 256
#define DOUT 256
#define NHEAD 8
#define DH 32
#define NTRK 256
#define LSEQ 256

// Scratch (device globals -- no allocations allowed)
__device__ __half g_valh[(size_t)NPTS * DIN];
__device__ __half g_wqkvh[3 * DOUT * DIN];
__device__ __half g_wlinh[DOUT * DIN];
__device__ __half g_qkvh[(size_t)NPTS * 3 * DOUT];
__device__ __half g_ctxh[(size_t)NPTS * DOUT];

// ---------------------------------------------------------------------------
__device__ __forceinline__ uint32_t smem_u32(const void* p) {
    uint32_t a;
    asm("{ .reg .u64 t; cvta.to.shared.u64 t, %1; cvt.u32.u64 %0, t; }" : "=r"(a) : "l"(p));
    return a;
}
__device__ __forceinline__ void cp_async16_s(uint32_t smem, const void* gmem) {
    asm volatile("cp.async.cg.shared.global [%0], [%1], 16;\n" :: "r"(smem), "l"(gmem));
}
__device__ __forceinline__ void cp_commit() { asm volatile("cp.async.commit_group;\n"); }
template <int N> __device__ __forceinline__ void cp_wait() {
    asm volatile("cp.async.wait_group %0;\n" :: "n"(N));
}
__device__ __forceinline__ void ldsm4(uint32_t& r0, uint32_t& r1, uint32_t& r2, uint32_t& r3,
                                      uint32_t addr) {
    asm volatile("ldmatrix.sync.aligned.m8n8.x4.shared.b16 {%0,%1,%2,%3}, [%4];"
                 : "=r"(r0), "=r"(r1), "=r"(r2), "=r"(r3) : "r"(addr));
}
__device__ __forceinline__ void mma16816(float* c, const uint32_t* a, uint32_t b0, uint32_t b1) {
    asm volatile(
        "mma.sync.aligned.m16n8k16.row.col.f32.f16.f16.f32 "
        "{%0,%1,%2,%3}, {%4,%5,%6,%7}, {%8,%9}, {%0,%1,%2,%3};"
        : "+f"(c[0]), "+f"(c[1]), "+f"(c[2]), "+f"(c[3])
        : "r"(a[0]), "r"(a[1]), "r"(a[2]), "r"(a[3]), "r"(b0), "r"(b1));
}

// ---------------------------------------------------------------------------
// fp32 -> fp16 convert
// ---------------------------------------------------------------------------
__global__ void f2h_kernel(const float* __restrict__ in, __half* __restrict__ out, int n4) {
    int i = blockIdx.x * blockDim.x + threadIdx.x;
    if (i < n4) {
        float4 v = reinterpret_cast<const float4*>(in)[i];
        reinterpret_cast<__half2*>(out)[2 * i]     = __floats2half2_rn(v.x, v.y);
        reinterpret_cast<__half2*>(out)[2 * i + 1] = __floats2half2_rn(v.z, v.w);
    }
}

// ---------------------------------------------------------------------------
// Hand-rolled mma.sync GEMM: C[M,Nc] = A[M,256] @ W^T + bias. W row-major [Nc,256].
// BM=128 BN=128 BK=64, 2-stage cp.async, 8 warps (2x4), warp tile 64x32.
// Explicit register double-buffering of ldmatrix fragments across k16 steps.
// ---------------------------------------------------------------------------
template <bool OUT_HALF>
__global__ __launch_bounds__(256, 2) void gemm_bias_kernel(
    const __half* __restrict__ A, const __half* __restrict__ W,
    const float* __restrict__ bias, void* __restrict__ Cout,
    int M, int Nc, int K)
{
    constexpr int BM = 128, BN = 128, BK = 64, LDT = 72;
    constexpr int STAGE_B = (BM + BN) * LDT * 2;           // 36864 bytes
    extern __shared__ __align__(16) unsigned char smbuf[]; // 2 stages = 73728
    __half* smh = reinterpret_cast<__half*>(smbuf);
    const uint32_t smbase = smem_u32(smh);

    const int tid = threadIdx.x;
    const int lane = tid & 31, warp = tid >> 5;
    const int wr = warp >> 2, wc = warp & 3;               // 2 (m) x 4 (n)
    const int g = lane >> 2, t4 = lane & 3;
    const int rowBase = blockIdx.y * BM;
    const int colBase = blockIdx.x * BN;
    const int NKB = K >> 6;                                // = 4

    auto load_stage = [&](int s, int kb) {
        uint32_t St = smbase + s * STAGE_B;
        const __half* Ag = A + (size_t)rowBase * K + kb * BK;
        const __half* Wg = W + (size_t)colBase * K + kb * BK;
#pragma unroll
        for (int i = 0; i < 8; i++) {
            int idx = tid + i * 256;                       // 0..2047
            int r = idx >> 3, c = idx & 7;
            const __half* src = (r < BM) ? (Ag + (size_t)r * K + c * 8)
                                         : (Wg + (size_t)(r - BM) * K + c * 8);
            cp_async16_s(St + (r * LDT + c * 8) * 2, src);
        }
        cp_commit();
    };

    // per-thread ldmatrix base offsets (bytes) within a stage
    const uint32_t aOff = ((wr * 64 + (lane & 15)) * LDT + (lane >> 4) * 8) * 2;
    const uint32_t bOff = (uint32_t)(BM * LDT * 2) +
                          ((wc * 32 + (lane & 15)) * LDT + (lane >> 4) * 8) * 2;

    uint32_t af[2][4][4];   // [buf][mtile][4]
    uint32_t bf[2][2][4];   // [buf][ngroup16][4]
    float    cc[4][4][4];   // [mtile][ntile][4]
#pragma unroll
    for (int i = 0; i < 4; i++)
#pragma unroll
        for (int j = 0; j < 4; j++)
#pragma unroll
            for (int e = 0; e < 4; e++) cc[i][j][e] = 0.0f;

#define LD_FRAGS(sbase, kk, buf)                                               \
    do {                                                                       \
        uint32_t _a = (sbase) + aOff + (kk) * 32;                              \
        ldsm4(af[buf][0][0], af[buf][0][1], af[buf][0][2], af[buf][0][3], _a); \
        ldsm4(af[buf][1][0], af[buf][1][1], af[buf][1][2], af[buf][1][3], _a + 16 * LDT * 2); \
        ldsm4(af[buf][2][0], af[buf][2][1], af[buf][2][2], af[buf][2][3], _a + 32 * LDT * 2); \
        ldsm4(af[buf][3][0], af[buf][3][1], af[buf][3][2], af[buf][3][3], _a + 48 * LDT * 2); \
        uint32_t _b = (sbase) + bOff + (kk) * 32;                              \
        ldsm4(bf[buf][0][0], bf[buf][0][1], bf[buf][0][2], bf[buf][0][3], _b); \
        ldsm4(bf[buf][1][0], bf[buf][1][1], bf[buf][1][2], bf[buf][1][3], _b + 16 * LDT * 2); \
    } while (0)

#define MMA_STEP(buf)                                                          \
    do {                                                                       \
        _Pragma("unroll")                                                      \
        for (int i = 0; i < 4; i++) {                                          \
            mma16816(cc[i][0], af[buf][i], bf[buf][0][0], bf[buf][0][2]);      \
            mma16816(cc[i][1], af[buf][i], bf[buf][0][1], bf[buf][0][3]);      \
            mma16816(cc[i][2], af[buf][i], bf[buf][1][0], bf[buf][1][2]);      \
            mma16816(cc[i][3], af[buf][i], bf[buf][1][1], bf[buf][1][3]);      \
        }                                                                      \
    } while (0)

    load_stage(0, 0);
    load_stage(1, 1);
    cp_wait<1>();
    __syncthreads();
    LD_FRAGS(smbase, 0, 0);

    for (int kb = 0; kb < NKB; kb++) {
        const uint32_t sbase = smbase + (kb & 1) * STAGE_B;
#pragma unroll
        for (int kk = 0; kk < 4; kk++) {
            if (kk < 3) LD_FRAGS(sbase, kk + 1, (kk + 1) & 1);
            MMA_STEP(kk & 1);
        }
        if (kb + 1 < NKB) {
            __syncthreads();   // all warps done reading stage (kb&1)
            if (kb + 2 < NKB) { load_stage(kb & 1, kb + 2); cp_wait<1>(); }
            else              { cp_wait<0>(); }
            __syncthreads();   // stage kb+1 visible to all warps
            LD_FRAGS(smbase + ((kb + 1) & 1) * STAGE_B, 0, 0);
        }
    }

    // epilogue: direct global stores from accumulator fragments
#pragma unroll
    for (int i = 0; i < 4; i++) {
        const int r0 = rowBase + wr * 64 + i * 16 + g;
#pragma unroll
        for (int j = 0; j < 4; j++) {
            const int col = colBase + wc * 32 + j * 8 + 2 * t4;
            const float b0 = bias[col], b1 = bias[col + 1];
            if (OUT_HALF) {
                __half* d = reinterpret_cast<__half*>(Cout);
                *reinterpret_cast<__half2*>(d + (size_t)r0 * Nc + col) =
                    __floats2half2_rn(cc[i][j][0] + b0, cc[i][j][1] + b1);
                *reinterpret_cast<__half2*>(d + (size_t)(r0 + 8) * Nc + col) =
                    __floats2half2_rn(cc[i][j][2] + b0, cc[i][j][3] + b1);
            } else {
                float* d = reinterpret_cast<float*>(Cout);
                *reinterpret_cast<float2*>(d + (size_t)r0 * Nc + col) =
                    make_float2(cc[i][j][0] + b0, cc[i][j][1] + b1);
                *reinterpret_cast<float2*>(d + (size_t)(r0 + 8) * Nc + col) =
                    make_float2(cc[i][j][2] + b0, cc[i][j][3] + b1);
            }
        }
    }
#undef LD_FRAGS
#undef MMA_STEP
}

// ---------------------------------------------------------------------------
// Attention: one block per (track, head); wmma QK^T with register softmax;
// unnormalized fp16 probs; PV wmma; normalize in epilogue.
// ---------------------------------------------------------------------------
__global__ __launch_bounds__(256) void attn_kernel(const __half* __restrict__ qkv,
                                                   __half* __restrict__ ctxout)
{
    constexpr int LDK = 40, LDP = 264;
    extern __shared__ __align__(16) unsigned char smbuf[];
    __half* Ksm = reinterpret_cast<__half*>(smbuf);
    __half* Vsm = Ksm + 256 * LDK;
    __half* Qsm = Vsm + 256 * LDK;
    __half* Psm = Qsm + 64 * LDK;
    float*  redM = reinterpret_cast<float*>(smbuf + 79872);
    float*  redS = redM + 128;

    const int tid = threadIdx.x, lane = tid & 31, warp = tid >> 5;
    const int g = lane >> 2, t4 = lane & 3;
    const int t = blockIdx.x >> 3, h = blockIdx.x & 7;
    const float scale = 0.17677669529663687f;

    {
        const uint4* ks = reinterpret_cast<const uint4*>(qkv + (size_t)(t * LSEQ + tid) * 768 + 256 + h * DH);
        const uint4* vs = reinterpret_cast<const uint4*>(qkv + (size_t)(t * LSEQ + tid) * 768 + 512 + h * DH);
        uint4* kd = reinterpret_cast<uint4*>(Ksm + tid * LDK);
        uint4* vd = reinterpret_cast<uint4*>(Vsm + tid * LDK);
#pragma unroll
        for (int q = 0; q < 4; q++) { kd[q] = ks[q]; vd[q] = vs[q]; }
    }

    for (int c0 = 0; c0 < LSEQ; c0 += 64) {
        {
            int r = tid >> 2, q = tid & 3;
            const uint4* qs = reinterpret_cast<const uint4*>(qkv + (size_t)(t * LSEQ + c0 + r) * 768 + h * DH);
            reinterpret_cast<uint4*>(Qsm + r * LDK)[q] = qs[q];
        }
        __syncthreads();

        const int wr = warp & 3, ch = warp >> 2;
        const int r0 = wr * 16, cb = ch * 128;
        wmma::fragment<wmma::accumulator, 16, 16, 16, float> S[8];
#pragma unroll
        for (int j = 0; j < 8; j++) wmma::fill_fragment(S[j], 0.0f);
#pragma unroll
        for (int kk = 0; kk < 32; kk += 16) {
            wmma::fragment<wmma::matrix_a, 16, 16, 16, __half, wmma::row_major> af;
            wmma::load_matrix_sync(af, Qsm + r0 * LDK + kk, LDK);
#pragma unroll
            for (int j = 0; j < 8; j++) {
                wmma::fragment<wmma::matrix_b, 16, 16, 16, __half, wmma::col_major> bf;
                wmma::load_matrix_sync(bf, Ksm + (cb + j * 16) * LDK + kk, LDK);
                wmma::mma_sync(S[j], af, bf, S[j]);
            }
        }

        float mx0 = -1e30f, mx1 = -1e30f;
#pragma unroll
        for (int j = 0; j < 8; j++) {
            mx0 = fmaxf(mx0, fmaxf(fmaxf(S[j].x[0], S[j].x[1]), fmaxf(S[j].x[4], S[j].x[5])));
            mx1 = fmaxf(mx1, fmaxf(fmaxf(S[j].x[2], S[j].x[3]), fmaxf(S[j].x[6], S[j].x[7])));
        }
#pragma unroll
        for (int o = 1; o <= 2; o <<= 1) {
            mx0 = fmaxf(mx0, __shfl_xor_sync(0xffffffffu, mx0, o));
            mx1 = fmaxf(mx1, __shfl_xor_sync(0xffffffffu, mx1, o));
        }
        if (t4 == 0) { redM[ch * 64 + r0 + g] = mx0; redM[ch * 64 + r0 + 8 + g] = mx1; }
        __syncthreads();

        const float gm0 = fmaxf(redM[r0 + g], redM[64 + r0 + g]);
        const float gm1 = fmaxf(redM[r0 + 8 + g], redM[64 + r0 + 8 + g]);

        float sm0 = 0.0f, sm1 = 0.0f;
#pragma unroll
        for (int j = 0; j < 8; j++) {
            float e0 = __expf((S[j].x[0] - gm0) * scale);
            float e1 = __expf((S[j].x[1] - gm0) * scale);
            float e2 = __expf((S[j].x[2] - gm1) * scale);
            float e3 = __expf((S[j].x[3] - gm1) * scale);
            float e4 = __expf((S[j].x[4] - gm0) * scale);
            float e5 = __expf((S[j].x[5] - gm0) * scale);
            float e6 = __expf((S[j].x[6] - gm1) * scale);
            float e7 = __expf((S[j].x[7] - gm1) * scale);
            sm0 += e0 + e1 + e4 + e5;
            sm1 += e2 + e3 + e6 + e7;
            __half2* p0 = reinterpret_cast<__half2*>(Psm + (r0 + g) * LDP + cb + j * 16 + 2 * t4);
            __half2* p1 = reinterpret_cast<__half2*>(Psm + (r0 + 8 + g) * LDP + cb + j * 16 + 2 * t4);
            p0[0] = __floats2half2_rn(e0, e1);
            p0[4] = __floats2half2_rn(e4, e5);
            p1[0] = __floats2half2_rn(e2, e3);
            p1[4] = __floats2half2_rn(e6, e7);
        }
#pragma unroll
        for (int o = 1; o <= 2; o <<= 1) {
            sm0 += __shfl_xor_sync(0xffffffffu, sm0, o);
            sm1 += __shfl_xor_sync(0xffffffffu, sm1, o);
        }
        if (t4 == 0) { redS[ch * 64 + r0 + g] = sm0; redS[ch * 64 + r0 + 8 + g] = sm1; }
        __syncthreads();

        {
            const int rp = (warp >> 1) * 16, ccol = (warp & 1) * 16;
            wmma::fragment<wmma::accumulator, 16, 16, 16, float> O;
            wmma::fill_fragment(O, 0.0f);
#pragma unroll
            for (int kk = 0; kk < 256; kk += 16) {
                wmma::fragment<wmma::matrix_a, 16, 16, 16, __half, wmma::row_major> af;
                wmma::load_matrix_sync(af, Psm + rp * LDP + kk, LDP);
                wmma::fragment<wmma::matrix_b, 16, 16, 16, __half, wmma::row_major> bf;
                wmma::load_matrix_sync(bf, Vsm + kk * LDK + ccol, LDK);
                wmma::mma_sync(O, af, bf, O);
            }
            const float inv0 = 1.0f / (redS[rp + g] + redS[64 + rp + g]);
            const float inv1 = 1.0f / (redS[rp + 8 + g] + redS[64 + rp + 8 + g]);
            __half* d0 = ctxout + (size_t)(t * LSEQ + c0 + rp + g) * DOUT + h * DH + ccol + 2 * t4;
            __half* d1 = ctxout + (size_t)(t * LSEQ + c0 + rp + 8 + g) * DOUT + h * DH + ccol + 2 * t4;
            *reinterpret_cast<__half2*>(d0)     = __floats2half2_rn(O.x[0] * inv0, O.x[1] * inv0);
            *reinterpret_cast<__half2*>(d0 + 8) = __floats2half2_rn(O.x[4] * inv0, O.x[5] * inv0);
            *reinterpret_cast<__half2*>(d1)     = __floats2half2_rn(O.x[2] * inv1, O.x[3] * inv1);
            *reinterpret_cast<__half2*>(d1 + 8) = __floats2half2_rn(O.x[6] * inv1, O.x[7] * inv1);
        }
        __syncthreads();
    }
}

// ---------------------------------------------------------------------------
extern "C" void kernel_launch(void* const* d_in, const int* in_sizes, int n_in,
                              void* d_out, int out_size)
{
    const float* values = (const float*)d_in[0];
    const float* wqkv   = (const float*)d_in[1];
    const float* bqkv   = (const float*)d_in[2];
    const float* wlin   = (const float*)d_in[3];
    const float* blin   = (const float*)d_in[4];

    void *p_valh, *p_wqkvh, *p_wlinh, *p_qkvh, *p_ctxh;
    cudaGetSymbolAddress(&p_valh, g_valh);
    cudaGetSymbolAddress(&p_wqkvh, g_wqkvh);
    cudaGetSymbolAddress(&p_wlinh, g_wlinh);
    cudaGetSymbolAddress(&p_qkvh, g_qkvh);
    cudaGetSymbolAddress(&p_ctxh, g_ctxh);

    const int GEMM_SMEM = 73728;
    cudaFuncSetAttribute(gemm_bias_kernel<true>,  cudaFuncAttributeMaxDynamicSharedMemorySize, GEMM_SMEM);
    cudaFuncSetAttribute(gemm_bias_kernel<false>, cudaFuncAttributeMaxDynamicSharedMemorySize, GEMM_SMEM);
    cudaFuncSetAttribute(attn_kernel, cudaFuncAttributeMaxDynamicSharedMemorySize, 80896);

    f2h_kernel<<<(NPTS * DIN / 4 + 255) / 256, 256>>>(values, (__half*)p_valh, NPTS * DIN / 4);
    f2h_kernel<<<(3 * DOUT * DIN / 4 + 255) / 256, 256>>>(wqkv, (__half*)p_wqkvh, 3 * DOUT * DIN / 4);
    f2h_kernel<<<(DOUT * DIN / 4 + 255) / 256, 256>>>(wlin, (__half*)p_wlinh, DOUT * DIN / 4);

    gemm_bias_kernel<true><<<dim3(768 / 128, NPTS / 128), 256, GEMM_SMEM>>>(
        (const __half*)p_valh, (const __half*)p_wqkvh, bqkv, p_qkvh, NPTS, 768, 256);

    attn_kernel<<<NTRK * NHEAD, 256, 80896>>>((const __half*)p_qkvh, (__half*)p_ctxh);

    gemm_bias_kernel<false><<<dim3(256 / 128, NPTS / 128), 256, GEMM_SMEM>>>(
        (const __half*)p_ctxh, (const __half*)p_wlinh, blin, d_out, NPTS, 256, 256);
}

// round 7
// speedup vs baseline: 1.9389x; 1.1342x over previous
#include <cuda_runtime.h>
#include <cuda_fp16.h>
#include <cstdint>

#define NPTS 65536
#define DIN 256
#define DOUT 256
#define NHEAD 8
#define DH 32
#define NTRK 256
#define LSEQ 256

// Scratch (device globals -- no allocations allowed)
__device__ __half g_valh[(size_t)NPTS * DIN];
__device__ __half g_wqkvh[3 * DOUT * DIN];
__device__ __half g_wlinh[DOUT * DIN];
__device__ __half g_qkvh[(size_t)NPTS * 3 * DOUT];
__device__ __half g_ctxh[(size_t)NPTS * DOUT];

// ---------------------------------------------------------------------------
__device__ __forceinline__ uint32_t smem_u32(const void* p) {
    uint32_t a;
    asm("{ .reg .u64 t; cvta.to.shared.u64 t, %1; cvt.u32.u64 %0, t; }" : "=r"(a) : "l"(p));
    return a;
}
__device__ __forceinline__ void cp_async16_s(uint32_t smem, const void* gmem) {
    asm volatile("cp.async.cg.shared.global [%0], [%1], 16;\n" :: "r"(smem), "l"(gmem));
}
__device__ __forceinline__ void cp_commit() { asm volatile("cp.async.commit_group;\n"); }
template <int N> __device__ __forceinline__ void cp_wait() {
    asm volatile("cp.async.wait_group %0;\n" :: "n"(N));
}
__device__ __forceinline__ void ldsm4(uint32_t& r0, uint32_t& r1, uint32_t& r2, uint32_t& r3,
                                      uint32_t addr) {
    asm volatile("ldmatrix.sync.aligned.m8n8.x4.shared.b16 {%0,%1,%2,%3}, [%4];"
                 : "=r"(r0), "=r"(r1), "=r"(r2), "=r"(r3) : "r"(addr));
}
__device__ __forceinline__ void ldsm4t(uint32_t& r0, uint32_t& r1, uint32_t& r2, uint32_t& r3,
                                       uint32_t addr) {
    asm volatile("ldmatrix.sync.aligned.m8n8.x4.trans.shared.b16 {%0,%1,%2,%3}, [%4];"
                 : "=r"(r0), "=r"(r1), "=r"(r2), "=r"(r3) : "r"(addr));
}
__device__ __forceinline__ void mma16816(float* c, const uint32_t* a, uint32_t b0, uint32_t b1) {
    asm volatile(
        "mma.sync.aligned.m16n8k16.row.col.f32.f16.f16.f32 "
        "{%0,%1,%2,%3}, {%4,%5,%6,%7}, {%8,%9}, {%0,%1,%2,%3};"
        : "+f"(c[0]), "+f"(c[1]), "+f"(c[2]), "+f"(c[3])
        : "r"(a[0]), "r"(a[1]), "r"(a[2]), "r"(a[3]), "r"(b0), "r"(b1));
}
__device__ __forceinline__ uint32_t h2u(__half2 h) {
    return *reinterpret_cast<uint32_t*>(&h);
}

// ---------------------------------------------------------------------------
// fp32 -> fp16 convert
// ---------------------------------------------------------------------------
__global__ void f2h_kernel(const float* __restrict__ in, __half* __restrict__ out, int n4) {
    int i = blockIdx.x * blockDim.x + threadIdx.x;
    if (i < n4) {
        float4 v = reinterpret_cast<const float4*>(in)[i];
        reinterpret_cast<__half2*>(out)[2 * i]     = __floats2half2_rn(v.x, v.y);
        reinterpret_cast<__half2*>(out)[2 * i + 1] = __floats2half2_rn(v.z, v.w);
    }
}

// ---------------------------------------------------------------------------
// Hand-rolled mma.sync GEMM: C[M,Nc] = A[M,256] @ W^T + bias. W row-major [Nc,256].
// BM=128 BN=128 BK=64, 2-stage cp.async, 8 warps (2x4), warp tile 64x32.
// ---------------------------------------------------------------------------
template <bool OUT_HALF>
__global__ __launch_bounds__(256, 2) void gemm_bias_kernel(
    const __half* __restrict__ A, const __half* __restrict__ W,
    const float* __restrict__ bias, void* __restrict__ Cout,
    int M, int Nc, int K)
{
    constexpr int BM = 128, BN = 128, BK = 64, LDT = 72;
    constexpr int STAGE_B = (BM + BN) * LDT * 2;           // 36864 bytes
    extern __shared__ __align__(16) unsigned char smbuf[]; // 2 stages = 73728
    __half* smh = reinterpret_cast<__half*>(smbuf);
    const uint32_t smbase = smem_u32(smh);

    const int tid = threadIdx.x;
    const int lane = tid & 31, warp = tid >> 5;
    const int wr = warp >> 2, wc = warp & 3;               // 2 (m) x 4 (n)
    const int g = lane >> 2, t4 = lane & 3;
    const int rowBase = blockIdx.y * BM;
    const int colBase = blockIdx.x * BN;
    const int NKB = K >> 6;                                // = 4

    auto load_stage = [&](int s, int kb) {
        uint32_t St = smbase + s * STAGE_B;
        const __half* Ag = A + (size_t)rowBase * K + kb * BK;
        const __half* Wg = W + (size_t)colBase * K + kb * BK;
#pragma unroll
        for (int i = 0; i < 8; i++) {
            int idx = tid + i * 256;                       // 0..2047
            int r = idx >> 3, c = idx & 7;
            const __half* src = (r < BM) ? (Ag + (size_t)r * K + c * 8)
                                         : (Wg + (size_t)(r - BM) * K + c * 8);
            cp_async16_s(St + (r * LDT + c * 8) * 2, src);
        }
        cp_commit();
    };

    const uint32_t aOff = ((wr * 64 + (lane & 15)) * LDT + (lane >> 4) * 8) * 2;
    const uint32_t bOff = (uint32_t)(BM * LDT * 2) +
                          ((wc * 32 + (lane & 15)) * LDT + (lane >> 4) * 8) * 2;

    uint32_t af[2][4][4];
    uint32_t bf[2][2][4];
    float    cc[4][4][4];
#pragma unroll
    for (int i = 0; i < 4; i++)
#pragma unroll
        for (int j = 0; j < 4; j++)
#pragma unroll
            for (int e = 0; e < 4; e++) cc[i][j][e] = 0.0f;

#define LD_FRAGS(sbase, kk, buf)                                               \
    do {                                                                       \
        uint32_t _a = (sbase) + aOff + (kk) * 32;                              \
        ldsm4(af[buf][0][0], af[buf][0][1], af[buf][0][2], af[buf][0][3], _a); \
        ldsm4(af[buf][1][0], af[buf][1][1], af[buf][1][2], af[buf][1][3], _a + 16 * LDT * 2); \
        ldsm4(af[buf][2][0], af[buf][2][1], af[buf][2][2], af[buf][2][3], _a + 32 * LDT * 2); \
        ldsm4(af[buf][3][0], af[buf][3][1], af[buf][3][2], af[buf][3][3], _a + 48 * LDT * 2); \
        uint32_t _b = (sbase) + bOff + (kk) * 32;                              \
        ldsm4(bf[buf][0][0], bf[buf][0][1], bf[buf][0][2], bf[buf][0][3], _b); \
        ldsm4(bf[buf][1][0], bf[buf][1][1], bf[buf][1][2], bf[buf][1][3], _b + 16 * LDT * 2); \
    } while (0)

#define MMA_STEP(buf)                                                          \
    do {                                                                       \
        _Pragma("unroll")                                                      \
        for (int i = 0; i < 4; i++) {                                          \
            mma16816(cc[i][0], af[buf][i], bf[buf][0][0], bf[buf][0][2]);      \
            mma16816(cc[i][1], af[buf][i], bf[buf][0][1], bf[buf][0][3]);      \
            mma16816(cc[i][2], af[buf][i], bf[buf][1][0], bf[buf][1][2]);      \
            mma16816(cc[i][3], af[buf][i], bf[buf][1][1], bf[buf][1][3]);      \
        }                                                                      \
    } while (0)

    load_stage(0, 0);
    load_stage(1, 1);
    cp_wait<1>();
    __syncthreads();
    LD_FRAGS(smbase, 0, 0);

    for (int kb = 0; kb < NKB; kb++) {
        const uint32_t sbase = smbase + (kb & 1) * STAGE_B;
#pragma unroll
        for (int kk = 0; kk < 4; kk++) {
            if (kk < 3) LD_FRAGS(sbase, kk + 1, (kk + 1) & 1);
            MMA_STEP(kk & 1);
        }
        if (kb + 1 < NKB) {
            __syncthreads();
            if (kb + 2 < NKB) { load_stage(kb & 1, kb + 2); cp_wait<1>(); }
            else              { cp_wait<0>(); }
            __syncthreads();
            LD_FRAGS(smbase + ((kb + 1) & 1) * STAGE_B, 0, 0);
        }
    }

#pragma unroll
    for (int i = 0; i < 4; i++) {
        const int r0 = rowBase + wr * 64 + i * 16 + g;
#pragma unroll
        for (int j = 0; j < 4; j++) {
            const int col = colBase + wc * 32 + j * 8 + 2 * t4;
            const float b0 = bias[col], b1 = bias[col + 1];
            if (OUT_HALF) {
                __half* d = reinterpret_cast<__half*>(Cout);
                *reinterpret_cast<__half2*>(d + (size_t)r0 * Nc + col) =
                    __floats2half2_rn(cc[i][j][0] + b0, cc[i][j][1] + b1);
                *reinterpret_cast<__half2*>(d + (size_t)(r0 + 8) * Nc + col) =
                    __floats2half2_rn(cc[i][j][2] + b0, cc[i][j][3] + b1);
            } else {
                float* d = reinterpret_cast<float*>(Cout);
                *reinterpret_cast<float2*>(d + (size_t)r0 * Nc + col) =
                    make_float2(cc[i][j][0] + b0, cc[i][j][1] + b1);
                *reinterpret_cast<float2*>(d + (size_t)(r0 + 8) * Nc + col) =
                    make_float2(cc[i][j][2] + b0, cc[i][j][3] + b1);
            }
        }
    }
#undef LD_FRAGS
#undef MMA_STEP
}

// ---------------------------------------------------------------------------
// Attention, flash-style: 1 block = (track, head), 128 threads, 4 warps.
// Q/K/V all resident in smem. Each warp owns 16 q-rows x 256 keys per strip
// (4 strips). Full softmax row in registers (reduce only over 4-lane groups);
// S accum packs directly into P A-operand fragments; V via ldmatrix.trans.
// One __syncthreads total.
// ---------------------------------------------------------------------------
__global__ __launch_bounds__(128) void attn_kernel(const __half* __restrict__ qkv,
                                                   __half* __restrict__ ctxout)
{
    constexpr int LDK = 40;
    extern __shared__ __align__(16) unsigned char smbuf[];   // 3 * 20480 = 61440
    __half* Ksm = reinterpret_cast<__half*>(smbuf);
    __half* Vsm = Ksm + 256 * LDK;
    __half* Qsm = Vsm + 256 * LDK;
    const uint32_t kb_ = smem_u32(Ksm), vb_ = smem_u32(Vsm), qb_ = smem_u32(Qsm);

    const int tid = threadIdx.x, lane = tid & 31, warp = tid >> 5;
    const int g = lane >> 2, t4 = lane & 3;
    const int t = blockIdx.x >> 3, h = blockIdx.x & 7;
    const float scale = 0.17677669529663687f;  // 1/sqrt(32)

    // cooperative load: Q, K, V (256 rows x 32 halves each)
    {
        const __half* base = qkv + (size_t)t * 256 * 768 + h * 32;
#pragma unroll
        for (int rr = 0; rr < 2; rr++) {
            int m = tid + rr * 128;
            const __half* row = base + (size_t)m * 768;
            uint32_t qd = qb_ + m * LDK * 2;
            uint32_t kd = kb_ + m * LDK * 2;
            uint32_t vd = vb_ + m * LDK * 2;
#pragma unroll
            for (int q = 0; q < 4; q++) {
                cp_async16_s(qd + q * 16, row + q * 8);
                cp_async16_s(kd + q * 16, row + 256 + q * 8);
                cp_async16_s(vd + q * 16, row + 512 + q * 8);
            }
        }
    }
    cp_commit();
    cp_wait<0>();
    __syncthreads();

#pragma unroll 1
    for (int s = 0; s < 4; s++) {
        const int r0 = s * 64 + warp * 16;

        // Q A-fragments for this strip (k=0..15 and k=16..31)
        uint32_t aq[2][4];
        uint32_t qaddr = qb_ + ((r0 + (lane & 15)) * LDK + (lane >> 4) * 8) * 2;
        ldsm4(aq[0][0], aq[0][1], aq[0][2], aq[0][3], qaddr);
        ldsm4(aq[1][0], aq[1][1], aq[1][2], aq[1][3], qaddr + 32);

        // S = Q K^T : 32 n8-tiles
        float S[32][4];
#pragma unroll
        for (int j = 0; j < 32; j++) { S[j][0] = S[j][1] = S[j][2] = S[j][3] = 0.0f; }
#pragma unroll
        for (int j = 0; j < 16; j++) {
            uint32_t b0[4], b1[4];
            uint32_t ka = kb_ + ((j * 16 + (lane & 15)) * LDK + (lane >> 4) * 8) * 2;
            ldsm4(b0[0], b0[1], b0[2], b0[3], ka);
            ldsm4(b1[0], b1[1], b1[2], b1[3], ka + 32);
            mma16816(S[2 * j],     aq[0], b0[0], b0[2]);
            mma16816(S[2 * j],     aq[1], b1[0], b1[2]);
            mma16816(S[2 * j + 1], aq[0], b0[1], b0[3]);
            mma16816(S[2 * j + 1], aq[1], b1[1], b1[3]);
        }

        // row max (row g -> c0,c1; row g+8 -> c2,c3), reduce over 4-lane group
        float mx0 = -1e30f, mx1 = -1e30f;
#pragma unroll
        for (int j = 0; j < 32; j++) {
            mx0 = fmaxf(mx0, fmaxf(S[j][0], S[j][1]));
            mx1 = fmaxf(mx1, fmaxf(S[j][2], S[j][3]));
        }
        mx0 = fmaxf(mx0, __shfl_xor_sync(0xffffffffu, mx0, 1));
        mx0 = fmaxf(mx0, __shfl_xor_sync(0xffffffffu, mx0, 2));
        mx1 = fmaxf(mx1, __shfl_xor_sync(0xffffffffu, mx1, 1));
        mx1 = fmaxf(mx1, __shfl_xor_sync(0xffffffffu, mx1, 2));

        // exp (unnormalized) -> pack P directly into m16k16 A-operand fragments
        float sum0 = 0.0f, sum1 = 0.0f;
        uint32_t pf[16][4];
#pragma unroll
        for (int b = 0; b < 16; b++) {
            float e00 = __expf((S[2 * b][0] - mx0) * scale);
            float e01 = __expf((S[2 * b][1] - mx0) * scale);
            float e02 = __expf((S[2 * b][2] - mx1) * scale);
            float e03 = __expf((S[2 * b][3] - mx1) * scale);
            float e10 = __expf((S[2 * b + 1][0] - mx0) * scale);
            float e11 = __expf((S[2 * b + 1][1] - mx0) * scale);
            float e12 = __expf((S[2 * b + 1][2] - mx1) * scale);
            float e13 = __expf((S[2 * b + 1][3] - mx1) * scale);
            sum0 += e00 + e01 + e10 + e11;
            sum1 += e02 + e03 + e12 + e13;
            pf[b][0] = h2u(__floats2half2_rn(e00, e01));   // (g,   k 2t4..)
            pf[b][1] = h2u(__floats2half2_rn(e02, e03));   // (g+8, k 2t4..)
            pf[b][2] = h2u(__floats2half2_rn(e10, e11));   // (g,   k 2t4+8..)
            pf[b][3] = h2u(__floats2half2_rn(e12, e13));   // (g+8, k 2t4+8..)
        }
        sum0 += __shfl_xor_sync(0xffffffffu, sum0, 1);
        sum0 += __shfl_xor_sync(0xffffffffu, sum0, 2);
        sum1 += __shfl_xor_sync(0xffffffffu, sum1, 1);
        sum1 += __shfl_xor_sync(0xffffffffu, sum1, 2);

        // O = P @ V  (16 x 32)
        float O[4][4];
#pragma unroll
        for (int j = 0; j < 4; j++) { O[j][0] = O[j][1] = O[j][2] = O[j][3] = 0.0f; }
#pragma unroll
        for (int b = 0; b < 16; b++) {
            uint32_t v0[4], v1[4];
            uint32_t va = vb_ + ((b * 16 + (lane & 15)) * LDK + (lane >> 4) * 8) * 2;
            ldsm4t(v0[0], v0[1], v0[2], v0[3], va);
            ldsm4t(v1[0], v1[1], v1[2], v1[3], va + 32);
            mma16816(O[0], pf[b], v0[0], v0[1]);
            mma16816(O[1], pf[b], v0[2], v0[3]);
            mma16816(O[2], pf[b], v1[0], v1[1]);
            mma16816(O[3], pf[b], v1[2], v1[3]);
        }

        const float inv0 = 1.0f / sum0;
        const float inv1 = 1.0f / sum1;
        __half* d0 = ctxout + (size_t)(t * 256 + r0 + g) * DOUT + h * 32 + 2 * t4;
        __half* d1 = ctxout + (size_t)(t * 256 + r0 + 8 + g) * DOUT + h * 32 + 2 * t4;
#pragma unroll
        for (int nt = 0; nt < 4; nt++) {
            *reinterpret_cast<__half2*>(d0 + nt * 8) =
                __floats2half2_rn(O[nt][0] * inv0, O[nt][1] * inv0);
            *reinterpret_cast<__half2*>(d1 + nt * 8) =
                __floats2half2_rn(O[nt][2] * inv1, O[nt][3] * inv1);
        }
    }
}

// ---------------------------------------------------------------------------
extern "C" void kernel_launch(void* const* d_in, const int* in_sizes, int n_in,
                              void* d_out, int out_size)
{
    const float* values = (const float*)d_in[0];
    const float* wqkv   = (const float*)d_in[1];
    const float* bqkv   = (const float*)d_in[2];
    const float* wlin   = (const float*)d_in[3];
    const float* blin   = (const float*)d_in[4];

    void *p_valh, *p_wqkvh, *p_wlinh, *p_qkvh, *p_ctxh;
    cudaGetSymbolAddress(&p_valh, g_valh);
    cudaGetSymbolAddress(&p_wqkvh, g_wqkvh);
    cudaGetSymbolAddress(&p_wlinh, g_wlinh);
    cudaGetSymbolAddress(&p_qkvh, g_qkvh);
    cudaGetSymbolAddress(&p_ctxh, g_ctxh);

    const int GEMM_SMEM = 73728;
    const int ATTN_SMEM = 61440;
    cudaFuncSetAttribute(gemm_bias_kernel<true>,  cudaFuncAttributeMaxDynamicSharedMemorySize, GEMM_SMEM);
    cudaFuncSetAttribute(gemm_bias_kernel<false>, cudaFuncAttributeMaxDynamicSharedMemorySize, GEMM_SMEM);
    cudaFuncSetAttribute(attn_kernel, cudaFuncAttributeMaxDynamicSharedMemorySize, ATTN_SMEM);

    f2h_kernel<<<(NPTS * DIN / 4 + 255) / 256, 256>>>(values, (__half*)p_valh, NPTS * DIN / 4);
    f2h_kernel<<<(3 * DOUT * DIN / 4 + 255) / 256, 256>>>(wqkv, (__half*)p_wqkvh, 3 * DOUT * DIN / 4);
    f2h_kernel<<<(DOUT * DIN / 4 + 255) / 256, 256>>>(wlin, (__half*)p_wlinh, DOUT * DIN / 4);

    gemm_bias_kernel<true><<<dim3(768 / 128, NPTS / 128), 256, GEMM_SMEM>>>(
        (const __half*)p_valh, (const __half*)p_wqkvh, bqkv, p_qkvh, NPTS, 768, 256);

    attn_kernel<<<NTRK * NHEAD, 128, ATTN_SMEM>>>((const __half*)p_qkvh, (__half*)p_ctxh);

    gemm_bias_kernel<false><<<dim3(256 / 128, NPTS / 128), 256, GEMM_SMEM>>>(
        (const __half*)p_ctxh, (const __half*)p_wlinh, blin, d_out, NPTS, 256, 256);
}

// round 8
// speedup vs baseline: 1.9766x; 1.0194x over previous
#include <cuda_runtime.h>
#include <cuda_fp16.h>
#include <cstdint>

#define NPTS 65536
#define DIN 256
#define DOUT 256
#define NHEAD 8
#define DH 32
#define NTRK 256
#define LSEQ 256

// Scratch (device globals -- no allocations allowed)
__device__ __half g_valh[(size_t)NPTS * DIN];
__device__ __half g_wqkvh[3 * DOUT * DIN];
__device__ __half g_wlinh[DOUT * DIN];
__device__ __half g_qkvh[(size_t)NPTS * 3 * DOUT];
__device__ __half g_ctxh[(size_t)NPTS * DOUT];

// ---------------------------------------------------------------------------
__device__ __forceinline__ uint32_t smem_u32(const void* p) {
    uint32_t a;
    asm("{ .reg .u64 t; cvta.to.shared.u64 t, %1; cvt.u32.u64 %0, t; }" : "=r"(a) : "l"(p));
    return a;
}
__device__ __forceinline__ void cp_async16_s(uint32_t smem, const void* gmem) {
    asm volatile("cp.async.cg.shared.global [%0], [%1], 16;\n" :: "r"(smem), "l"(gmem));
}
__device__ __forceinline__ void cp_commit() { asm volatile("cp.async.commit_group;\n"); }
template <int N> __device__ __forceinline__ void cp_wait() {
    asm volatile("cp.async.wait_group %0;\n" :: "n"(N));
}
__device__ __forceinline__ void ldsm4(uint32_t& r0, uint32_t& r1, uint32_t& r2, uint32_t& r3,
                                      uint32_t addr) {
    asm volatile("ldmatrix.sync.aligned.m8n8.x4.shared.b16 {%0,%1,%2,%3}, [%4];"
                 : "=r"(r0), "=r"(r1), "=r"(r2), "=r"(r3) : "r"(addr));
}
__device__ __forceinline__ void ldsm4t(uint32_t& r0, uint32_t& r1, uint32_t& r2, uint32_t& r3,
                                       uint32_t addr) {
    asm volatile("ldmatrix.sync.aligned.m8n8.x4.trans.shared.b16 {%0,%1,%2,%3}, [%4];"
                 : "=r"(r0), "=r"(r1), "=r"(r2), "=r"(r3) : "r"(addr));
}
__device__ __forceinline__ void mma16816(float* c, const uint32_t* a, uint32_t b0, uint32_t b1) {
    asm volatile(
        "mma.sync.aligned.m16n8k16.row.col.f32.f16.f16.f32 "
        "{%0,%1,%2,%3}, {%4,%5,%6,%7}, {%8,%9}, {%0,%1,%2,%3};"
        : "+f"(c[0]), "+f"(c[1]), "+f"(c[2]), "+f"(c[3])
        : "r"(a[0]), "r"(a[1]), "r"(a[2]), "r"(a[3]), "r"(b0), "r"(b1));
}
__device__ __forceinline__ uint32_t h2u(__half2 h) {
    return *reinterpret_cast<uint32_t*>(&h);
}

// ---------------------------------------------------------------------------
// fp32 -> fp16 convert
// ---------------------------------------------------------------------------
__global__ void f2h_kernel(const float* __restrict__ in, __half* __restrict__ out, int n4) {
    int i = blockIdx.x * blockDim.x + threadIdx.x;
    if (i < n4) {
        float4 v = reinterpret_cast<const float4*>(in)[i];
        reinterpret_cast<__half2*>(out)[2 * i]     = __floats2half2_rn(v.x, v.y);
        reinterpret_cast<__half2*>(out)[2 * i + 1] = __floats2half2_rn(v.z, v.w);
    }
}

// ---------------------------------------------------------------------------
// mma.sync GEMM: C[M,Nc] = A[M,256] @ W^T + bias. W row-major [Nc,256].
// BM=128 BN=128 BK=64; 128 threads, 4 warps in 2x2 grid, warp tile 64x64
// (8 LDSM.x4 per 32 HMMA -> smem traffic per FLOP cut 1.5x vs 64x32).
// 2-stage cp.async, register double-buffered fragments. 2 CTAs/SM.
// ---------------------------------------------------------------------------
template <bool OUT_HALF>
__global__ __launch_bounds__(128, 2) void gemm_bias_kernel(
    const __half* __restrict__ A, const __half* __restrict__ W,
    const float* __restrict__ bias, void* __restrict__ Cout,
    int M, int Nc, int K)
{
    constexpr int BM = 128, BN = 128, BK = 64, LDT = 72;
    constexpr int STAGE_B = (BM + BN) * LDT * 2;           // 36864 bytes
    extern __shared__ __align__(16) unsigned char smbuf[]; // 2 stages = 73728
    const uint32_t smbase = smem_u32(smbuf);

    const int tid = threadIdx.x;
    const int lane = tid & 31, warp = tid >> 5;
    const int wr = warp >> 1, wc = warp & 1;               // 2 (m) x 2 (n)
    const int g = lane >> 2, t4 = lane & 3;
    const int rowBase = blockIdx.y * BM;
    const int colBase = blockIdx.x * BN;
    const int NKB = K >> 6;                                // = 4

    auto load_stage = [&](int s, int kb) {
        uint32_t St = smbase + s * STAGE_B;
        const __half* Ag = A + (size_t)rowBase * K + kb * BK;
        const __half* Wg = W + (size_t)colBase * K + kb * BK;
#pragma unroll
        for (int i = 0; i < 16; i++) {
            int idx = tid + i * 128;                       // 0..2047
            int r = idx >> 3, c = idx & 7;
            const __half* src = (r < BM) ? (Ag + (size_t)r * K + c * 8)
                                         : (Wg + (size_t)(r - BM) * K + c * 8);
            cp_async16_s(St + (r * LDT + c * 8) * 2, src);
        }
        cp_commit();
    };

    const uint32_t aOff = ((wr * 64 + (lane & 15)) * LDT + (lane >> 4) * 8) * 2;
    const uint32_t bOff = (uint32_t)(BM * LDT * 2) +
                          ((wc * 64 + (lane & 15)) * LDT + (lane >> 4) * 8) * 2;

    uint32_t af[2][4][4];   // [buf][mtile][4]
    uint32_t bf[2][4][4];   // [buf][n16group][4]
    float    cc[4][8][4];   // [mtile][n8tile][4]
#pragma unroll
    for (int i = 0; i < 4; i++)
#pragma unroll
        for (int j = 0; j < 8; j++)
#pragma unroll
            for (int e = 0; e < 4; e++) cc[i][j][e] = 0.0f;

#define LD_FRAGS(sbase, kk, buf)                                               \
    do {                                                                       \
        uint32_t _a = (sbase) + aOff + (kk) * 32;                              \
        ldsm4(af[buf][0][0], af[buf][0][1], af[buf][0][2], af[buf][0][3], _a); \
        ldsm4(af[buf][1][0], af[buf][1][1], af[buf][1][2], af[buf][1][3], _a + 16 * LDT * 2); \
        ldsm4(af[buf][2][0], af[buf][2][1], af[buf][2][2], af[buf][2][3], _a + 32 * LDT * 2); \
        ldsm4(af[buf][3][0], af[buf][3][1], af[buf][3][2], af[buf][3][3], _a + 48 * LDT * 2); \
        uint32_t _b = (sbase) + bOff + (kk) * 32;                              \
        ldsm4(bf[buf][0][0], bf[buf][0][1], bf[buf][0][2], bf[buf][0][3], _b); \
        ldsm4(bf[buf][1][0], bf[buf][1][1], bf[buf][1][2], bf[buf][1][3], _b + 16 * LDT * 2); \
        ldsm4(bf[buf][2][0], bf[buf][2][1], bf[buf][2][2], bf[buf][2][3], _b + 32 * LDT * 2); \
        ldsm4(bf[buf][3][0], bf[buf][3][1], bf[buf][3][2], bf[buf][3][3], _b + 48 * LDT * 2); \
    } while (0)

#define MMA_STEP(buf)                                                          \
    do {                                                                       \
        _Pragma("unroll")                                                      \
        for (int i = 0; i < 4; i++) {                                          \
            _Pragma("unroll")                                                  \
            for (int j = 0; j < 4; j++) {                                      \
                mma16816(cc[i][2 * j],     af[buf][i], bf[buf][j][0], bf[buf][j][2]); \
                mma16816(cc[i][2 * j + 1], af[buf][i], bf[buf][j][1], bf[buf][j][3]); \
            }                                                                  \
        }                                                                      \
    } while (0)

    load_stage(0, 0);
    load_stage(1, 1);
    cp_wait<1>();
    __syncthreads();
    LD_FRAGS(smbase, 0, 0);

    for (int kb = 0; kb < NKB; kb++) {
        const uint32_t sbase = smbase + (kb & 1) * STAGE_B;
#pragma unroll
        for (int kk = 0; kk < 4; kk++) {
            if (kk < 3) LD_FRAGS(sbase, kk + 1, (kk + 1) & 1);
            MMA_STEP(kk & 1);
        }
        if (kb + 1 < NKB) {
            __syncthreads();
            if (kb + 2 < NKB) { load_stage(kb & 1, kb + 2); cp_wait<1>(); }
            else              { cp_wait<0>(); }
            __syncthreads();
            LD_FRAGS(smbase + ((kb + 1) & 1) * STAGE_B, 0, 0);
        }
    }

    // epilogue: direct global stores from accumulator fragments
#pragma unroll
    for (int i = 0; i < 4; i++) {
        const int r0 = rowBase + wr * 64 + i * 16 + g;
#pragma unroll
        for (int j = 0; j < 8; j++) {
            const int col = colBase + wc * 64 + j * 8 + 2 * t4;
            const float b0 = bias[col], b1 = bias[col + 1];
            if (OUT_HALF) {
                __half* d = reinterpret_cast<__half*>(Cout);
                *reinterpret_cast<__half2*>(d + (size_t)r0 * Nc + col) =
                    __floats2half2_rn(cc[i][j][0] + b0, cc[i][j][1] + b1);
                *reinterpret_cast<__half2*>(d + (size_t)(r0 + 8) * Nc + col) =
                    __floats2half2_rn(cc[i][j][2] + b0, cc[i][j][3] + b1);
            } else {
                float* d = reinterpret_cast<float*>(Cout);
                *reinterpret_cast<float2*>(d + (size_t)r0 * Nc + col) =
                    make_float2(cc[i][j][0] + b0, cc[i][j][1] + b1);
                *reinterpret_cast<float2*>(d + (size_t)(r0 + 8) * Nc + col) =
                    make_float2(cc[i][j][2] + b0, cc[i][j][3] + b1);
            }
        }
    }
#undef LD_FRAGS
#undef MMA_STEP
}

// ---------------------------------------------------------------------------
// Attention, flash-style: 1 block = (track, head), 128 threads, 4 warps.
// Q/K/V resident in smem; full softmax row in registers; S accum packs into
// P A-operand fragments; V via ldmatrix.trans. One __syncthreads total.
// ---------------------------------------------------------------------------
__global__ __launch_bounds__(128) void attn_kernel(const __half* __restrict__ qkv,
                                                   __half* __restrict__ ctxout)
{
    constexpr int LDK = 40;
    extern __shared__ __align__(16) unsigned char smbuf[];   // 3 * 20480 = 61440
    __half* Ksm = reinterpret_cast<__half*>(smbuf);
    __half* Vsm = Ksm + 256 * LDK;
    __half* Qsm = Vsm + 256 * LDK;
    const uint32_t kb_ = smem_u32(Ksm), vb_ = smem_u32(Vsm), qb_ = smem_u32(Qsm);

    const int tid = threadIdx.x, lane = tid & 31, warp = tid >> 5;
    const int g = lane >> 2, t4 = lane & 3;
    const int t = blockIdx.x >> 3, h = blockIdx.x & 7;
    const float scale = 0.17677669529663687f;  // 1/sqrt(32)

    {
        const __half* base = qkv + (size_t)t * 256 * 768 + h * 32;
#pragma unroll
        for (int rr = 0; rr < 2; rr++) {
            int m = tid + rr * 128;
            const __half* row = base + (size_t)m * 768;
            uint32_t qd = qb_ + m * LDK * 2;
            uint32_t kd = kb_ + m * LDK * 2;
            uint32_t vd = vb_ + m * LDK * 2;
#pragma unroll
            for (int q = 0; q < 4; q++) {
                cp_async16_s(qd + q * 16, row + q * 8);
                cp_async16_s(kd + q * 16, row + 256 + q * 8);
                cp_async16_s(vd + q * 16, row + 512 + q * 8);
            }
        }
    }
    cp_commit();
    cp_wait<0>();
    __syncthreads();

#pragma unroll 1
    for (int s = 0; s < 4; s++) {
        const int r0 = s * 64 + warp * 16;

        uint32_t aq[2][4];
        uint32_t qaddr = qb_ + ((r0 + (lane & 15)) * LDK + (lane >> 4) * 8) * 2;
        ldsm4(aq[0][0], aq[0][1], aq[0][2], aq[0][3], qaddr);
        ldsm4(aq[1][0], aq[1][1], aq[1][2], aq[1][3], qaddr + 32);

        float S[32][4];
#pragma unroll
        for (int j = 0; j < 32; j++) { S[j][0] = S[j][1] = S[j][2] = S[j][3] = 0.0f; }
#pragma unroll
        for (int j = 0; j < 16; j++) {
            uint32_t b0[4], b1[4];
            uint32_t ka = kb_ + ((j * 16 + (lane & 15)) * LDK + (lane >> 4) * 8) * 2;
            ldsm4(b0[0], b0[1], b0[2], b0[3], ka);
            ldsm4(b1[0], b1[1], b1[2], b1[3], ka + 32);
            mma16816(S[2 * j],     aq[0], b0[0], b0[2]);
            mma16816(S[2 * j],     aq[1], b1[0], b1[2]);
            mma16816(S[2 * j + 1], aq[0], b0[1], b0[3]);
            mma16816(S[2 * j + 1], aq[1], b1[1], b1[3]);
        }

        float mx0 = -1e30f, mx1 = -1e30f;
#pragma unroll
        for (int j = 0; j < 32; j++) {
            mx0 = fmaxf(mx0, fmaxf(S[j][0], S[j][1]));
            mx1 = fmaxf(mx1, fmaxf(S[j][2], S[j][3]));
        }
        mx0 = fmaxf(mx0, __shfl_xor_sync(0xffffffffu, mx0, 1));
        mx0 = fmaxf(mx0, __shfl_xor_sync(0xffffffffu, mx0, 2));
        mx1 = fmaxf(mx1, __shfl_xor_sync(0xffffffffu, mx1, 1));
        mx1 = fmaxf(mx1, __shfl_xor_sync(0xffffffffu, mx1, 2));

        float sum0 = 0.0f, sum1 = 0.0f;
        uint32_t pf[16][4];
#pragma unroll
        for (int b = 0; b < 16; b++) {
            float e00 = __expf((S[2 * b][0] - mx0) * scale);
            float e01 = __expf((S[2 * b][1] - mx0) * scale);
            float e02 = __expf((S[2 * b][2] - mx1) * scale);
            float e03 = __expf((S[2 * b][3] - mx1) * scale);
            float e10 = __expf((S[2 * b + 1][0] - mx0) * scale);
            float e11 = __expf((S[2 * b + 1][1] - mx0) * scale);
            float e12 = __expf((S[2 * b + 1][2] - mx1) * scale);
            float e13 = __expf((S[2 * b + 1][3] - mx1) * scale);
            sum0 += e00 + e01 + e10 + e11;
            sum1 += e02 + e03 + e12 + e13;
            pf[b][0] = h2u(__floats2half2_rn(e00, e01));
            pf[b][1] = h2u(__floats2half2_rn(e02, e03));
            pf[b][2] = h2u(__floats2half2_rn(e10, e11));
            pf[b][3] = h2u(__floats2half2_rn(e12, e13));
        }
        sum0 += __shfl_xor_sync(0xffffffffu, sum0, 1);
        sum0 += __shfl_xor_sync(0xffffffffu, sum0, 2);
        sum1 += __shfl_xor_sync(0xffffffffu, sum1, 1);
        sum1 += __shfl_xor_sync(0xffffffffu, sum1, 2);

        float O[4][4];
#pragma unroll
        for (int j = 0; j < 4; j++) { O[j][0] = O[j][1] = O[j][2] = O[j][3] = 0.0f; }
#pragma unroll
        for (int b = 0; b < 16; b++) {
            uint32_t v0[4], v1[4];
            uint32_t va = vb_ + ((b * 16 + (lane & 15)) * LDK + (lane >> 4) * 8) * 2;
            ldsm4t(v0[0], v0[1], v0[2], v0[3], va);
            ldsm4t(v1[0], v1[1], v1[2], v1[3], va + 32);
            mma16816(O[0], pf[b], v0[0], v0[1]);
            mma16816(O[1], pf[b], v0[2], v0[3]);
            mma16816(O[2], pf[b], v1[0], v1[1]);
            mma16816(O[3], pf[b], v1[2], v1[3]);
        }

        const float inv0 = 1.0f / sum0;
        const float inv1 = 1.0f / sum1;
        __half* d0 = ctxout + (size_t)(t * 256 + r0 + g) * DOUT + h * 32 + 2 * t4;
        __half* d1 = ctxout + (size_t)(t * 256 + r0 + 8 + g) * DOUT + h * 32 + 2 * t4;
#pragma unroll
        for (int nt = 0; nt < 4; nt++) {
            *reinterpret_cast<__half2*>(d0 + nt * 8) =
                __floats2half2_rn(O[nt][0] * inv0, O[nt][1] * inv0);
            *reinterpret_cast<__half2*>(d1 + nt * 8) =
                __floats2half2_rn(O[nt][2] * inv1, O[nt][3] * inv1);
        }
    }
}

// ---------------------------------------------------------------------------
extern "C" void kernel_launch(void* const* d_in, const int* in_sizes, int n_in,
                              void* d_out, int out_size)
{
    const float* values = (const float*)d_in[0];
    const float* wqkv   = (const float*)d_in[1];
    const float* bqkv   = (const float*)d_in[2];
    const float* wlin   = (const float*)d_in[3];
    const float* blin   = (const float*)d_in[4];

    void *p_valh, *p_wqkvh, *p_wlinh, *p_qkvh, *p_ctxh;
    cudaGetSymbolAddress(&p_valh, g_valh);
    cudaGetSymbolAddress(&p_wqkvh, g_wqkvh);
    cudaGetSymbolAddress(&p_wlinh, g_wlinh);
    cudaGetSymbolAddress(&p_qkvh, g_qkvh);
    cudaGetSymbolAddress(&p_ctxh, g_ctxh);

    const int GEMM_SMEM = 73728;
    const int ATTN_SMEM = 61440;
    cudaFuncSetAttribute(gemm_bias_kernel<true>,  cudaFuncAttributeMaxDynamicSharedMemorySize, GEMM_SMEM);
    cudaFuncSetAttribute(gemm_bias_kernel<false>, cudaFuncAttributeMaxDynamicSharedMemorySize, GEMM_SMEM);
    cudaFuncSetAttribute(attn_kernel, cudaFuncAttributeMaxDynamicSharedMemorySize, ATTN_SMEM);

    f2h_kernel<<<(NPTS * DIN / 4 + 255) / 256, 256>>>(values, (__half*)p_valh, NPTS * DIN / 4);
    f2h_kernel<<<(3 * DOUT * DIN / 4 + 255) / 256, 256>>>(wqkv, (__half*)p_wqkvh, 3 * DOUT * DIN / 4);
    f2h_kernel<<<(DOUT * DIN / 4 + 255) / 256, 256>>>(wlin, (__half*)p_wlinh, DOUT * DIN / 4);

    gemm_bias_kernel<true><<<dim3(768 / 128, NPTS / 128), 128, GEMM_SMEM>>>(
        (const __half*)p_valh, (const __half*)p_wqkvh, bqkv, p_qkvh, NPTS, 768, 256);

    attn_kernel<<<NTRK * NHEAD, 128, ATTN_SMEM>>>((const __half*)p_qkvh, (__half*)p_ctxh);

    gemm_bias_kernel<false><<<dim3(256 / 128, NPTS / 128), 128, GEMM_SMEM>>>(
        (const __half*)p_ctxh, (const __half*)p_wlinh, blin, d_out, NPTS, 256, 256);
}

// round 9
// speedup vs baseline: 2.1940x; 1.1100x over previous
#include <cuda_runtime.h>
#include <cuda_fp16.h>
#include <cstdint>

#define NPTS 65536
#define DIN 256
#define DOUT 256
#define NHEAD 8
#define DH 32
#define NTRK 256
#define LSEQ 256

// Scratch (device globals -- no allocations allowed)
__device__ __half g_valh[(size_t)NPTS * DIN];
__device__ __half g_wqkvh[3 * DOUT * DIN];
__device__ __half g_wlinh[DOUT * DIN];
__device__ __half g_qkvh[(size_t)NPTS * 3 * DOUT];
__device__ __half g_ctxh[(size_t)NPTS * DOUT];

// ---------------------------------------------------------------------------
__device__ __forceinline__ uint32_t smem_u32(const void* p) {
    uint32_t a;
    asm("{ .reg .u64 t; cvta.to.shared.u64 t, %1; cvt.u32.u64 %0, t; }" : "=r"(a) : "l"(p));
    return a;
}
__device__ __forceinline__ void cp_async16_s(uint32_t smem, const void* gmem) {
    asm volatile("cp.async.cg.shared.global [%0], [%1], 16;\n" :: "r"(smem), "l"(gmem));
}
__device__ __forceinline__ void cp_commit() { asm volatile("cp.async.commit_group;\n"); }
template <int N> __device__ __forceinline__ void cp_wait() {
    asm volatile("cp.async.wait_group %0;\n" :: "n"(N));
}
__device__ __forceinline__ void ldsm4(uint32_t& r0, uint32_t& r1, uint32_t& r2, uint32_t& r3,
                                      uint32_t addr) {
    asm volatile("ldmatrix.sync.aligned.m8n8.x4.shared.b16 {%0,%1,%2,%3}, [%4];"
                 : "=r"(r0), "=r"(r1), "=r"(r2), "=r"(r3) : "r"(addr));
}
__device__ __forceinline__ void ldsm4t(uint32_t& r0, uint32_t& r1, uint32_t& r2, uint32_t& r3,
                                       uint32_t addr) {
    asm volatile("ldmatrix.sync.aligned.m8n8.x4.trans.shared.b16 {%0,%1,%2,%3}, [%4];"
                 : "=r"(r0), "=r"(r1), "=r"(r2), "=r"(r3) : "r"(addr));
}
__device__ __forceinline__ void mma16816(float* c, const uint32_t* a, uint32_t b0, uint32_t b1) {
    asm volatile(
        "mma.sync.aligned.m16n8k16.row.col.f32.f16.f16.f32 "
        "{%0,%1,%2,%3}, {%4,%5,%6,%7}, {%8,%9}, {%0,%1,%2,%3};"
        : "+f"(c[0]), "+f"(c[1]), "+f"(c[2]), "+f"(c[3])
        : "r"(a[0]), "r"(a[1]), "r"(a[2]), "r"(a[3]), "r"(b0), "r"(b1));
}
__device__ __forceinline__ uint32_t h2u(__half2 h) {
    return *reinterpret_cast<uint32_t*>(&h);
}
__device__ __forceinline__ uint32_t ex2_f16x2(uint32_t x) {
    uint32_t r;
    asm("ex2.approx.f16x2 %0, %1;" : "=r"(r) : "r"(x));
    return r;
}

// ---------------------------------------------------------------------------
// fp32 -> fp16 convert (single kernel for all three tensors)
// ---------------------------------------------------------------------------
#define N4_VAL  (NPTS * DIN / 4)                 // 4194304
#define N4_WQKV (3 * DOUT * DIN / 4)             // 49152
#define N4_WLIN (DOUT * DIN / 4)                 // 16384
__global__ void f2h_all_kernel(const float* __restrict__ v, const float* __restrict__ wq,
                               const float* __restrict__ wl, __half* __restrict__ ov,
                               __half* __restrict__ owq, __half* __restrict__ owl) {
    int i = blockIdx.x * blockDim.x + threadIdx.x;
    const float* in;
    __half* out;
    int j = i;
    if (i < N4_VAL) { in = v; out = ov; }
    else if (i < N4_VAL + N4_WQKV) { in = wq; out = owq; j = i - N4_VAL; }
    else if (i < N4_VAL + N4_WQKV + N4_WLIN) { in = wl; out = owl; j = i - N4_VAL - N4_WQKV; }
    else return;
    float4 x = reinterpret_cast<const float4*>(in)[j];
    reinterpret_cast<__half2*>(out)[2 * j]     = __floats2half2_rn(x.x, x.y);
    reinterpret_cast<__half2*>(out)[2 * j + 1] = __floats2half2_rn(x.z, x.w);
}

// ---------------------------------------------------------------------------
// mma.sync GEMM: C[M,Nc] = A[M,256] @ W^T + bias. W row-major [Nc,256].
// BM=128 BN=128 BK=64; 128 threads, 4 warps 2x2, warp tile 64x64.
// ---------------------------------------------------------------------------
template <bool OUT_HALF>
__global__ __launch_bounds__(128, 2) void gemm_bias_kernel(
    const __half* __restrict__ A, const __half* __restrict__ W,
    const float* __restrict__ bias, void* __restrict__ Cout,
    int M, int Nc, int K)
{
    constexpr int BM = 128, BN = 128, BK = 64, LDT = 72;
    constexpr int STAGE_B = (BM + BN) * LDT * 2;
    extern __shared__ __align__(16) unsigned char smbuf[];
    const uint32_t smbase = smem_u32(smbuf);

    const int tid = threadIdx.x;
    const int lane = tid & 31, warp = tid >> 5;
    const int wr = warp >> 1, wc = warp & 1;
    const int g = lane >> 2, t4 = lane & 3;
    const int rowBase = blockIdx.y * BM;
    const int colBase = blockIdx.x * BN;
    const int NKB = K >> 6;

    auto load_stage = [&](int s, int kb) {
        uint32_t St = smbase + s * STAGE_B;
        const __half* Ag = A + (size_t)rowBase * K + kb * BK;
        const __half* Wg = W + (size_t)colBase * K + kb * BK;
#pragma unroll
        for (int i = 0; i < 16; i++) {
            int idx = tid + i * 128;
            int r = idx >> 3, c = idx & 7;
            const __half* src = (r < BM) ? (Ag + (size_t)r * K + c * 8)
                                         : (Wg + (size_t)(r - BM) * K + c * 8);
            cp_async16_s(St + (r * LDT + c * 8) * 2, src);
        }
        cp_commit();
    };

    const uint32_t aOff = ((wr * 64 + (lane & 15)) * LDT + (lane >> 4) * 8) * 2;
    const uint32_t bOff = (uint32_t)(BM * LDT * 2) +
                          ((wc * 64 + (lane & 15)) * LDT + (lane >> 4) * 8) * 2;

    uint32_t af[2][4][4];
    uint32_t bf[2][4][4];
    float    cc[4][8][4];
#pragma unroll
    for (int i = 0; i < 4; i++)
#pragma unroll
        for (int j = 0; j < 8; j++)
#pragma unroll
            for (int e = 0; e < 4; e++) cc[i][j][e] = 0.0f;

#define LD_FRAGS(sbase, kk, buf)                                               \
    do {                                                                       \
        uint32_t _a = (sbase) + aOff + (kk) * 32;                              \
        ldsm4(af[buf][0][0], af[buf][0][1], af[buf][0][2], af[buf][0][3], _a); \
        ldsm4(af[buf][1][0], af[buf][1][1], af[buf][1][2], af[buf][1][3], _a + 16 * LDT * 2); \
        ldsm4(af[buf][2][0], af[buf][2][1], af[buf][2][2], af[buf][2][3], _a + 32 * LDT * 2); \
        ldsm4(af[buf][3][0], af[buf][3][1], af[buf][3][2], af[buf][3][3], _a + 48 * LDT * 2); \
        uint32_t _b = (sbase) + bOff + (kk) * 32;                              \
        ldsm4(bf[buf][0][0], bf[buf][0][1], bf[buf][0][2], bf[buf][0][3], _b); \
        ldsm4(bf[buf][1][0], bf[buf][1][1], bf[buf][1][2], bf[buf][1][3], _b + 16 * LDT * 2); \
        ldsm4(bf[buf][2][0], bf[buf][2][1], bf[buf][2][2], bf[buf][2][3], _b + 32 * LDT * 2); \
        ldsm4(bf[buf][3][0], bf[buf][3][1], bf[buf][3][2], bf[buf][3][3], _b + 48 * LDT * 2); \
    } while (0)

#define MMA_STEP(buf)                                                          \
    do {                                                                       \
        _Pragma("unroll")                                                      \
        for (int i = 0; i < 4; i++) {                                          \
            _Pragma("unroll")                                                  \
            for (int j = 0; j < 4; j++) {                                      \
                mma16816(cc[i][2 * j],     af[buf][i], bf[buf][j][0], bf[buf][j][2]); \
                mma16816(cc[i][2 * j + 1], af[buf][i], bf[buf][j][1], bf[buf][j][3]); \
            }                                                                  \
        }                                                                      \
    } while (0)

    load_stage(0, 0);
    load_stage(1, 1);
    cp_wait<1>();
    __syncthreads();
    LD_FRAGS(smbase, 0, 0);

    for (int kb = 0; kb < NKB; kb++) {
        const uint32_t sbase = smbase + (kb & 1) * STAGE_B;
#pragma unroll
        for (int kk = 0; kk < 4; kk++) {
            if (kk < 3) LD_FRAGS(sbase, kk + 1, (kk + 1) & 1);
            MMA_STEP(kk & 1);
        }
        if (kb + 1 < NKB) {
            __syncthreads();
            if (kb + 2 < NKB) { load_stage(kb & 1, kb + 2); cp_wait<1>(); }
            else              { cp_wait<0>(); }
            __syncthreads();
            LD_FRAGS(smbase + ((kb + 1) & 1) * STAGE_B, 0, 0);
        }
    }

#pragma unroll
    for (int i = 0; i < 4; i++) {
        const int r0 = rowBase + wr * 64 + i * 16 + g;
#pragma unroll
        for (int j = 0; j < 8; j++) {
            const int col = colBase + wc * 64 + j * 8 + 2 * t4;
            const float b0 = bias[col], b1 = bias[col + 1];
            if (OUT_HALF) {
                __half* d = reinterpret_cast<__half*>(Cout);
                *reinterpret_cast<__half2*>(d + (size_t)r0 * Nc + col) =
                    __floats2half2_rn(cc[i][j][0] + b0, cc[i][j][1] + b1);
                *reinterpret_cast<__half2*>(d + (size_t)(r0 + 8) * Nc + col) =
                    __floats2half2_rn(cc[i][j][2] + b0, cc[i][j][3] + b1);
            } else {
                float* d = reinterpret_cast<float*>(Cout);
                *reinterpret_cast<float2*>(d + (size_t)r0 * Nc + col) =
                    make_float2(cc[i][j][0] + b0, cc[i][j][1] + b1);
                *reinterpret_cast<float2*>(d + (size_t)(r0 + 8) * Nc + col) =
                    make_float2(cc[i][j][2] + b0, cc[i][j][3] + b1);
            }
        }
    }
#undef LD_FRAGS
#undef MMA_STEP
}

// ---------------------------------------------------------------------------
// Attention, flash-style. Softmax via ex2.approx.f16x2 (2 exps per MUFU,
// scale*log2e folded into one FFMA per element); row sums via ones-MMA
// (P_b @ ones accumulated in f32 alongside PV) -- no FADD chain, no shuffles.
// ---------------------------------------------------------------------------
__global__ __launch_bounds__(128) void attn_kernel(const __half* __restrict__ qkv,
                                                   __half* __restrict__ ctxout)
{
    constexpr int LDK = 40;
    extern __shared__ __align__(16) unsigned char smbuf[];   // 3 * 20480 = 61440
    __half* Ksm = reinterpret_cast<__half*>(smbuf);
    __half* Vsm = Ksm + 256 * LDK;
    __half* Qsm = Vsm + 256 * LDK;
    const uint32_t kb_ = smem_u32(Ksm), vb_ = smem_u32(Vsm), qb_ = smem_u32(Qsm);

    const int tid = threadIdx.x, lane = tid & 31, warp = tid >> 5;
    const int g = lane >> 2, t4 = lane & 3;
    const int t = blockIdx.x >> 3, h = blockIdx.x & 7;
    const float cs = 0.17677669529663687f * 1.4426950408889634f;  // scale * log2(e)
    const uint32_t ONES = 0x3C003C00u;  // half2(1,1)

    {
        const __half* base = qkv + (size_t)t * 256 * 768 + h * 32;
#pragma unroll
        for (int rr = 0; rr < 2; rr++) {
            int m = tid + rr * 128;
            const __half* row = base + (size_t)m * 768;
            uint32_t qd = qb_ + m * LDK * 2;
            uint32_t kd = kb_ + m * LDK * 2;
            uint32_t vd = vb_ + m * LDK * 2;
#pragma unroll
            for (int q = 0; q < 4; q++) {
                cp_async16_s(qd + q * 16, row + q * 8);
                cp_async16_s(kd + q * 16, row + 256 + q * 8);
                cp_async16_s(vd + q * 16, row + 512 + q * 8);
            }
        }
    }
    cp_commit();
    cp_wait<0>();
    __syncthreads();

#pragma unroll 1
    for (int s = 0; s < 4; s++) {
        const int r0 = s * 64 + warp * 16;

        uint32_t aq[2][4];
        uint32_t qaddr = qb_ + ((r0 + (lane & 15)) * LDK + (lane >> 4) * 8) * 2;
        ldsm4(aq[0][0], aq[0][1], aq[0][2], aq[0][3], qaddr);
        ldsm4(aq[1][0], aq[1][1], aq[1][2], aq[1][3], qaddr + 32);

        float S[32][4];
#pragma unroll
        for (int j = 0; j < 32; j++) { S[j][0] = S[j][1] = S[j][2] = S[j][3] = 0.0f; }
#pragma unroll
        for (int j = 0; j < 16; j++) {
            uint32_t b0[4], b1[4];
            uint32_t ka = kb_ + ((j * 16 + (lane & 15)) * LDK + (lane >> 4) * 8) * 2;
            ldsm4(b0[0], b0[1], b0[2], b0[3], ka);
            ldsm4(b1[0], b1[1], b1[2], b1[3], ka + 32);
            mma16816(S[2 * j],     aq[0], b0[0], b0[2]);
            mma16816(S[2 * j],     aq[1], b1[0], b1[2]);
            mma16816(S[2 * j + 1], aq[0], b0[1], b0[3]);
            mma16816(S[2 * j + 1], aq[1], b1[1], b1[3]);
        }

        // row max (4-lane group reduction)
        float mx0 = -1e30f, mx1 = -1e30f;
#pragma unroll
        for (int j = 0; j < 32; j++) {
            mx0 = fmaxf(mx0, fmaxf(S[j][0], S[j][1]));
            mx1 = fmaxf(mx1, fmaxf(S[j][2], S[j][3]));
        }
        mx0 = fmaxf(mx0, __shfl_xor_sync(0xffffffffu, mx0, 1));
        mx0 = fmaxf(mx0, __shfl_xor_sync(0xffffffffu, mx0, 2));
        mx1 = fmaxf(mx1, __shfl_xor_sync(0xffffffffu, mx1, 1));
        mx1 = fmaxf(mx1, __shfl_xor_sync(0xffffffffu, mx1, 2));
        const float mb0 = mx0 * cs, mb1 = mx1 * cs;

        // P = exp2((S - m) * cs) computed 2-at-a-time in f16
        uint32_t pf[16][4];
#pragma unroll
        for (int b = 0; b < 16; b++) {
            pf[b][0] = ex2_f16x2(h2u(__floats2half2_rn(
                fmaf(S[2 * b][0], cs, -mb0), fmaf(S[2 * b][1], cs, -mb0))));
            pf[b][1] = ex2_f16x2(h2u(__floats2half2_rn(
                fmaf(S[2 * b][2], cs, -mb1), fmaf(S[2 * b][3], cs, -mb1))));
            pf[b][2] = ex2_f16x2(h2u(__floats2half2_rn(
                fmaf(S[2 * b + 1][0], cs, -mb0), fmaf(S[2 * b + 1][1], cs, -mb0))));
            pf[b][3] = ex2_f16x2(h2u(__floats2half2_rn(
                fmaf(S[2 * b + 1][2], cs, -mb1), fmaf(S[2 * b + 1][3], cs, -mb1))));
        }

        // O = P @ V ; row sums via P @ ones (exact f32 accumulation)
        float O[4][4];
        float sm[4];
#pragma unroll
        for (int j = 0; j < 4; j++) { O[j][0] = O[j][1] = O[j][2] = O[j][3] = 0.0f; }
        sm[0] = sm[1] = sm[2] = sm[3] = 0.0f;
#pragma unroll
        for (int b = 0; b < 16; b++) {
            uint32_t v0[4], v1[4];
            uint32_t va = vb_ + ((b * 16 + (lane & 15)) * LDK + (lane >> 4) * 8) * 2;
            ldsm4t(v0[0], v0[1], v0[2], v0[3], va);
            ldsm4t(v1[0], v1[1], v1[2], v1[3], va + 32);
            mma16816(O[0], pf[b], v0[0], v0[1]);
            mma16816(O[1], pf[b], v0[2], v0[3]);
            mma16816(O[2], pf[b], v1[0], v1[1]);
            mma16816(O[3], pf[b], v1[2], v1[3]);
            mma16816(sm, pf[b], ONES, ONES);
        }

        const float inv0 = 1.0f / sm[0];
        const float inv1 = 1.0f / sm[2];
        __half* d0 = ctxout + (size_t)(t * 256 + r0 + g) * DOUT + h * 32 + 2 * t4;
        __half* d1 = ctxout + (size_t)(t * 256 + r0 + 8 + g) * DOUT + h * 32 + 2 * t4;
#pragma unroll
        for (int nt = 0; nt < 4; nt++) {
            *reinterpret_cast<__half2*>(d0 + nt * 8) =
                __floats2half2_rn(O[nt][0] * inv0, O[nt][1] * inv0);
            *reinterpret_cast<__half2*>(d1 + nt * 8) =
                __floats2half2_rn(O[nt][2] * inv1, O[nt][3] * inv1);
        }
    }
}

// ---------------------------------------------------------------------------
extern "C" void kernel_launch(void* const* d_in, const int* in_sizes, int n_in,
                              void* d_out, int out_size)
{
    const float* values = (const float*)d_in[0];
    const float* wqkv   = (const float*)d_in[1];
    const float* bqkv   = (const float*)d_in[2];
    const float* wlin   = (const float*)d_in[3];
    const float* blin   = (const float*)d_in[4];

    void *p_valh, *p_wqkvh, *p_wlinh, *p_qkvh, *p_ctxh;
    cudaGetSymbolAddress(&p_valh, g_valh);
    cudaGetSymbolAddress(&p_wqkvh, g_wqkvh);
    cudaGetSymbolAddress(&p_wlinh, g_wlinh);
    cudaGetSymbolAddress(&p_qkvh, g_qkvh);
    cudaGetSymbolAddress(&p_ctxh, g_ctxh);

    const int GEMM_SMEM = 73728;
    const int ATTN_SMEM = 61440;
    cudaFuncSetAttribute(gemm_bias_kernel<true>,  cudaFuncAttributeMaxDynamicSharedMemorySize, GEMM_SMEM);
    cudaFuncSetAttribute(gemm_bias_kernel<false>, cudaFuncAttributeMaxDynamicSharedMemorySize, GEMM_SMEM);
    cudaFuncSetAttribute(attn_kernel, cudaFuncAttributeMaxDynamicSharedMemorySize, ATTN_SMEM);

    const int N4_TOTAL = N4_VAL + N4_WQKV + N4_WLIN;
    f2h_all_kernel<<<(N4_TOTAL + 255) / 256, 256>>>(
        values, wqkv, wlin, (__half*)p_valh, (__half*)p_wqkvh, (__half*)p_wlinh);

    gemm_bias_kernel<true><<<dim3(768 / 128, NPTS / 128), 128, GEMM_SMEM>>>(
        (const __half*)p_valh, (const __half*)p_wqkvh, bqkv, p_qkvh, NPTS, 768, 256);

    attn_kernel<<<NTRK * NHEAD, 128, ATTN_SMEM>>>((const __half*)p_qkvh, (__half*)p_ctxh);

    gemm_bias_kernel<false><<<dim3(256 / 128, NPTS / 128), 128, GEMM_SMEM>>>(
        (const __half*)p_ctxh, (const __half*)p_wlinh, blin, d_out, NPTS, 256, 256);
}